// round 16
// baseline (speedup 1.0000x reference)
#include <cuda_runtime.h>
#include <cstdint>

#define BS   256
#define SEQ  512
#define H    768
#define GRID_N 144

// Scratch (no allocations allowed)
__device__ float g_emb[BS * H];               // gathered "embraced" rows
__device__ float g_Sp[4][3][BS * H];          // [ksplit][group] partial products
__device__ unsigned g_bar_cnt[2];             // zero-init; atomicInc wraps -> self-reset
__device__ unsigned g_bar_gen[2];             // monotonic generation

// ---------------------------------------------------------------------------
// Threefry-2x32, 20 rounds, key = (0, 42), partitionable scheme:
//   bits32(i) = x0 ^ x1 of threefry2x32(key, (0, i))
// ---------------------------------------------------------------------------
__device__ __forceinline__ uint32_t rotl32(uint32_t x, int r) {
    return (x << r) | (x >> (32 - r));
}

__device__ __forceinline__ uint32_t threefry_bits_partitionable(uint32_t i) {
    const uint32_t k0 = 0u, k1 = 42u;
    const uint32_t ks2 = 0x1BD11BDAu ^ k0 ^ k1;
    uint32_t x0 = 0u + k0;
    uint32_t x1 = i  + k1;

#define TF_BLOCK(r0_, r1_, r2_, r3_)                                   \
    x0 += x1; x1 = rotl32(x1, r0_); x1 ^= x0;                          \
    x0 += x1; x1 = rotl32(x1, r1_); x1 ^= x0;                          \
    x0 += x1; x1 = rotl32(x1, r2_); x1 ^= x0;                          \
    x0 += x1; x1 = rotl32(x1, r3_); x1 ^= x0;

    TF_BLOCK(13, 15, 26, 6)   x0 += k1;  x1 += ks2 + 1u;
    TF_BLOCK(17, 29, 16, 24)  x0 += ks2; x1 += k0  + 2u;
    TF_BLOCK(13, 15, 26, 6)   x0 += k0;  x1 += k1  + 3u;
    TF_BLOCK(17, 29, 16, 24)  x0 += k1;  x1 += ks2 + 4u;
    TF_BLOCK(13, 15, 26, 6)   x0 += ks2; x1 += k0  + 5u;
#undef TF_BLOCK
    return x0 ^ x1;
}

// fast tanh via MUFU.EX2: exact limits at +-inf
__device__ __forceinline__ float fast_tanh(float x) {
    return 1.0f - 2.0f / (__expf(2.0f * x) + 1.0f);
}

// ---------------------------------------------------------------------------
// Software grid barrier. All GRID_N blocks co-resident (144 <= 148 SMs at
// occupancy 1), so spin-wait cannot deadlock. atomicInc wraps the counter to
// zero after GRID_N arrivals (self-resetting across graph replays); the
// generation word increases monotonically.
// ---------------------------------------------------------------------------
__device__ __forceinline__ void grid_barrier(int id) {
    __syncthreads();
    if (threadIdx.x == 0) {
        __threadfence();                                  // publish this block's writes
        const unsigned my_gen = atomicAdd(&g_bar_gen[id], 0u);
        if (atomicInc(&g_bar_cnt[id], GRID_N - 1) == GRID_N - 1) {
            atomicAdd(&g_bar_gen[id], 1u);                // release
        } else {
            while (atomicAdd(&g_bar_gen[id], 0u) == my_gen) { __nanosleep(64); }
        }
        __threadfence();
    }
    __syncthreads();
}

// ---------------------------------------------------------------------------
// GEMM machinery (Phase B): BM=128, BN=128, BK=16, 4-stage cp.async,
// warp tile 64x32, K-split 4 -> 144 tiles. Raw f32 bits -> mma.tf32.
// ---------------------------------------------------------------------------
#define BK     16
#define NITQ   ((H / 4) / BK)   // 12 iterations per K-quarter
#define NSTAGE 4
#define APAD   20
#define BPAD   136
#define A_WORDS (128 * APAD)   // 2560
#define B_WORDS (BK * BPAD)    // 2176
#define GEMM_SMEM (NSTAGE * (A_WORDS + B_WORDS) * 4)   // 75776 bytes

__device__ __forceinline__ void cp16(uint32_t saddr, const void* gaddr) {
    asm volatile("cp.async.ca.shared.global [%0], [%1], 16;\n"
                 :: "r"(saddr), "l"(gaddr));
}
__device__ __forceinline__ void cp_commit() {
    asm volatile("cp.async.commit_group;\n");
}
template <int N>
__device__ __forceinline__ void cp_wait() {
    asm volatile("cp.async.wait_group %0;\n" :: "n"(N));
}

__device__ __forceinline__ void mma_tf32(float* d, const uint32_t* a, const uint32_t* b) {
    asm volatile(
        "mma.sync.aligned.m16n8k8.row.col.f32.tf32.tf32.f32 "
        "{%0,%1,%2,%3}, {%4,%5,%6,%7}, {%8,%9}, {%0,%1,%2,%3};\n"
        : "+f"(d[0]), "+f"(d[1]), "+f"(d[2]), "+f"(d[3])
        : "r"(a[0]), "r"(a[1]), "r"(a[2]), "r"(a[3]), "r"(b[0]), "r"(b[1]));
}

// ---------------------------------------------------------------------------
// THE fused kernel: Phase A gather | barrier | Phase B GEMM | barrier |
// Phase C epilogue.  144 blocks x 256 threads, 76KB dynamic smem.
// ---------------------------------------------------------------------------
__global__ void __launch_bounds__(256, 1)
fused_kernel(const float* __restrict__ tokens,
             const int*   __restrict__ mask,
             const float* __restrict__ cls,
             const float* __restrict__ W,
             const float* __restrict__ bias,
             const float* __restrict__ v,
             float*       __restrict__ out) {
    extern __shared__ uint32_t sm[];
    const int tid = threadIdx.x;
    const int bid = blockIdx.x;

    // batch slice for phases A and C: [b_start, b_end) (1 or 2 batches)
    const int b_start = (bid * 16) / 9;          // = bid*256/144
    const int b_end   = ((bid + 1) * 16) / 9;

    // ======================= Phase A: length + gather =======================
    {
        int* s_len = (int*)sm;
        for (int b = b_start; b < b_end; b++) {
            if (tid == 0) *s_len = SEQ;
            __syncthreads();
            if (mask[b * SEQ + tid] == 0)       atomicMin(s_len, tid);
            if (mask[b * SEQ + tid + 256] == 0) atomicMin(s_len, tid + 256);
            __syncthreads();
            const int   len  = *s_len;
            const float lenf = (float)len;
            const size_t rowb = (size_t)b * SEQ * H;

            int   jj[3];
            int   idx[3];
#pragma unroll
            for (int s = 0; s < 3; s++) {
                const int j = tid + s * 256;
                const int i = b * H + j;
                const uint32_t bits = threefry_bits_partitionable((uint32_t)i);
                const float u = __uint_as_float((bits >> 9) | 0x3f800000u) - 1.0f;
                int id2 = (int)floorf(u * lenf);
                if (id2 > len - 1) id2 = len - 1;
                jj[s] = j; idx[s] = id2;
            }
            float val[3];
#pragma unroll
            for (int s = 0; s < 3; s++)
                val[s] = __ldcg(&tokens[rowb + (size_t)idx[s] * H + jj[s]]);
#pragma unroll
            for (int s = 0; s < 3; s++)
                g_emb[b * H + jj[s]] = val[s];
            __syncthreads();   // s_len reuse for next batch
        }
    }

    grid_barrier(0);

    // ======================= Phase B: TF32 GEMM =======================
    {
        uint32_t* As = sm;
        uint32_t* Bs = sm + NSTAGE * A_WORDS;

        const int bx = bid % 6;                    // n tile
        const int by = bid / 6;                    // 0..23
        const int g     = by >> 3;                 // group 0..2
        const int m0    = ((by >> 2) & 1) * 128;
        const int split = by & 3;
        const int n0    = bx * 128;
        const int kb    = split * (H / 4);

        const float* __restrict__ A  = (g == 2) ? g_emb : cls;
        const float* __restrict__ Wg = W + (g == 0 ? 0 : (size_t)H * H);

        const int warp = tid >> 5;
        const int lane = tid & 31;
        const int wm   = (warp & 1) * 64;
        const int wn   = (warp >> 1) * 32;
        const int grp  = lane >> 2;
        const int tig  = lane & 3;

        const int a_r = tid >> 1;
        const int a_c = (tid & 1) * 8;
        const int b_r = tid >> 4;
        const int b_c = (tid & 15) * 8;

        const float* a_src = &A[(m0 + a_r) * H + kb + a_c];
        const float* b_src = &Wg[(size_t)(kb + b_r) * H + n0 + b_c];

        const uint32_t s_as = (uint32_t)__cvta_generic_to_shared(As) +
                              (uint32_t)((a_r * APAD + a_c) * 4);
        const uint32_t s_bs = (uint32_t)__cvta_generic_to_shared(Bs) +
                              (uint32_t)((b_r * BPAD + b_c) * 4);

        float acc[4][4][4];
#pragma unroll
        for (int mi = 0; mi < 4; mi++)
#pragma unroll
            for (int ni = 0; ni < 4; ni++)
#pragma unroll
                for (int r = 0; r < 4; r++) acc[mi][ni][r] = 0.0f;

#pragma unroll
        for (int s = 0; s < NSTAGE - 1; s++) {
            cp16(s_as + (uint32_t)(s * A_WORDS * 4),      a_src + s * BK);
            cp16(s_as + (uint32_t)(s * A_WORDS * 4) + 16, a_src + s * BK + 4);
            cp16(s_bs + (uint32_t)(s * B_WORDS * 4),      b_src + (size_t)(s * BK) * H);
            cp16(s_bs + (uint32_t)(s * B_WORDS * 4) + 16, b_src + (size_t)(s * BK) * H + 4);
            cp_commit();
        }

        for (int it = 0; it < NITQ; it++) {
            cp_wait<NSTAGE - 2>();
            __syncthreads();

            const int nx = it + NSTAGE - 1;
            if (nx < NITQ) {
                const int buf = nx & (NSTAGE - 1);
                cp16(s_as + (uint32_t)(buf * A_WORDS * 4),      a_src + nx * BK);
                cp16(s_as + (uint32_t)(buf * A_WORDS * 4) + 16, a_src + nx * BK + 4);
                cp16(s_bs + (uint32_t)(buf * B_WORDS * 4),      b_src + (size_t)(nx * BK) * H);
                cp16(s_bs + (uint32_t)(buf * B_WORDS * 4) + 16, b_src + (size_t)(nx * BK) * H + 4);
            }
            cp_commit();

            const uint32_t* Asb = As + (it & (NSTAGE - 1)) * A_WORDS;
            const uint32_t* Bsb = Bs + (it & (NSTAGE - 1)) * B_WORDS;
#pragma unroll
            for (int ks = 0; ks < BK; ks += 8) {
                uint32_t afr[4][4];
#pragma unroll
                for (int mi = 0; mi < 4; mi++) {
                    const int rbase = (wm + mi * 16 + grp) * APAD + ks + tig;
                    afr[mi][0] = Asb[rbase];
                    afr[mi][1] = Asb[rbase + 8 * APAD];
                    afr[mi][2] = Asb[rbase + 4];
                    afr[mi][3] = Asb[rbase + 8 * APAD + 4];
                }
                uint32_t bfr[4][2];
#pragma unroll
                for (int ni = 0; ni < 4; ni++) {
                    const int cbase = (ks + tig) * BPAD + wn + ni * 8 + grp;
                    bfr[ni][0] = Bsb[cbase];
                    bfr[ni][1] = Bsb[cbase + 4 * BPAD];
                }
#pragma unroll
                for (int mi = 0; mi < 4; mi++)
#pragma unroll
                    for (int ni = 0; ni < 4; ni++)
                        mma_tf32(acc[mi][ni], afr[mi], bfr[ni]);
            }
        }

        float* __restrict__ Cp = g_Sp[split][g];
#pragma unroll
        for (int mi = 0; mi < 4; mi++) {
#pragma unroll
            for (int ni = 0; ni < 4; ni++) {
                const int col = n0 + wn + ni * 8 + tig * 2;
                const int r0  = m0 + wm + mi * 16 + grp;
                *reinterpret_cast<float2*>(&Cp[(size_t)r0 * H + col]) =
                    make_float2(acc[mi][ni][0], acc[mi][ni][1]);
                *reinterpret_cast<float2*>(&Cp[(size_t)(r0 + 8) * H + col]) =
                    make_float2(acc[mi][ni][2], acc[mi][ni][3]);
            }
        }
    }

    grid_barrier(1);

    // ======================= Phase C: energy + combine =======================
    {
        float* r0 = (float*)sm;            // [8]
        float* r1 = (float*)sm + 8;        // [8]
        float* s_alpha = (float*)sm + 16;

        const int w = tid >> 5, l = tid & 31;

        for (int b = b_start; b < b_end; b++) {
            float p0 = 0.f, p1 = 0.f;
#pragma unroll
            for (int s = 0; s < 3; s++) {
                const int j = tid + s * 256;
                const size_t base = (size_t)b * H + j;
                float s0 = 0.f, s1 = 0.f, s2 = 0.f;
#pragma unroll
                for (int ks = 0; ks < 4; ks++) {
                    s0 += g_Sp[ks][0][base];
                    s1 += g_Sp[ks][1][base];
                    s2 += g_Sp[ks][2][base];
                }
                const float bi = bias[j];
                const float vv = v[j];
                p0 += fast_tanh(s0 + s1 + bi) * vv;
                p1 += fast_tanh(s0 + s2 + bi) * vv;
            }
#pragma unroll
            for (int off = 16; off > 0; off >>= 1) {
                p0 += __shfl_down_sync(0xffffffffu, p0, off);
                p1 += __shfl_down_sync(0xffffffffu, p1, off);
            }
            __syncthreads();    // smem reuse (GEMM buffers / previous batch)
            if (l == 0) { r0[w] = p0; r1[w] = p1; }
            __syncthreads();
            if (tid == 0) {
                float e0 = 0.f, e1 = 0.f;
#pragma unroll
                for (int i = 0; i < 8; i++) { e0 += r0[i]; e1 += r1[i]; }
                const float m  = fmaxf(e0, e1);
                const float w0 = __expf(e0 - m);
                const float w1 = __expf(e1 - m);
                *s_alpha = w0 / (w0 + w1);
            }
            __syncthreads();
            const float a0 = *s_alpha;
#pragma unroll
            for (int s = 0; s < 3; s++) {
                const size_t base = (size_t)b * H + tid + s * 256;
                out[base] = a0 * cls[base] + (1.0f - a0) * g_emb[base];
            }
        }
    }
}

// ---------------------------------------------------------------------------
// kernel_launch — inputs identified BY ELEMENT COUNT
// ---------------------------------------------------------------------------
extern "C" void kernel_launch(void* const* d_in, const int* in_sizes, int n_in,
                              void* d_out, int out_size) {
    const float* tokens = nullptr;
    const float* cls    = nullptr;
    const int*   mask   = nullptr;
    const float* W      = nullptr;
    const float* bias   = nullptr;
    const float* v      = nullptr;

    for (int i = 0; i < n_in; i++) {
        const int sz = in_sizes[i];
        if      (sz == BS * SEQ * H) tokens = (const float*)d_in[i];
        else if (sz == BS * H)       cls    = (const float*)d_in[i];
        else if (sz == BS * SEQ)     mask   = (const int*)  d_in[i];
        else if (sz == 2 * H * H)    W      = (const float*)d_in[i];
        else if (sz == H) {
            if (bias == nullptr)     bias   = (const float*)d_in[i];
            else                     v      = (const float*)d_in[i];
        }
    }
    float* out = (float*)d_out;

    // idempotent; capture-safe (not a stream op)
    cudaFuncSetAttribute(fused_kernel,
                         cudaFuncAttributeMaxDynamicSharedMemorySize, GEMM_SMEM);

    fused_kernel<<<GRID_N, 256, GEMM_SMEM>>>(tokens, mask, cls, W, bias, v, out);
}

// round 17
// speedup vs baseline: 1.2931x; 1.2931x over previous
#include <cuda_runtime.h>
#include <cstdint>

#define BS   256
#define SEQ  512
#define H    768

// Scratch (no allocations allowed)
__device__ float g_emb[BS * H];          // gathered "embraced" rows
__device__ float g_S[3 * BS * H];        // S0 = cls@Wtop, S1 = cls@Wbot, S2 = emb@Wbot

// ---------------------------------------------------------------------------
// Threefry-2x32, 20 rounds, key = (0, 42), partitionable scheme:
//   bits32(i) = x0 ^ x1 of threefry2x32(key, (0, i))
// ---------------------------------------------------------------------------
__device__ __forceinline__ uint32_t rotl32(uint32_t x, int r) {
    return (x << r) | (x >> (32 - r));
}

__device__ __forceinline__ uint32_t threefry_bits_partitionable(uint32_t i) {
    const uint32_t k0 = 0u, k1 = 42u;
    const uint32_t ks2 = 0x1BD11BDAu ^ k0 ^ k1;
    uint32_t x0 = 0u + k0;
    uint32_t x1 = i  + k1;

#define TF_BLOCK(r0_, r1_, r2_, r3_)                                   \
    x0 += x1; x1 = rotl32(x1, r0_); x1 ^= x0;                          \
    x0 += x1; x1 = rotl32(x1, r1_); x1 ^= x0;                          \
    x0 += x1; x1 = rotl32(x1, r2_); x1 ^= x0;                          \
    x0 += x1; x1 = rotl32(x1, r3_); x1 ^= x0;

    TF_BLOCK(13, 15, 26, 6)   x0 += k1;  x1 += ks2 + 1u;
    TF_BLOCK(17, 29, 16, 24)  x0 += ks2; x1 += k0  + 2u;
    TF_BLOCK(13, 15, 26, 6)   x0 += k0;  x1 += k1  + 3u;
    TF_BLOCK(17, 29, 16, 24)  x0 += k1;  x1 += ks2 + 4u;
    TF_BLOCK(13, 15, 26, 6)   x0 += ks2; x1 += k0  + 5u;
#undef TF_BLOCK
    return x0 ^ x1;
}

// fast tanh via MUFU.EX2: exact limits at +-inf
__device__ __forceinline__ float fast_tanh(float x) {
    return 1.0f - 2.0f / (__expf(2.0f * x) + 1.0f);
}

// ---------------------------------------------------------------------------
// Kernel 1: fused length-scan + gather (R8 config — keep chip-exclusive
// during the load burst; PDL successors only SPIN while this runs).
// ---------------------------------------------------------------------------
__global__ void __launch_bounds__(384, 4)
prep_kernel(const float* __restrict__ tokens,
            const int*   __restrict__ mask) {
    const int b   = blockIdx.x;
    const int tid = threadIdx.x;   // 0..383

    __shared__ int s_len;
    if (tid == 0) s_len = SEQ;
    __syncthreads();
    if (mask[b * SEQ + tid] == 0) atomicMin(&s_len, tid);
    {
        const int t2 = tid + 384;
        if (t2 < SEQ && mask[b * SEQ + t2] == 0) atomicMin(&s_len, t2);
    }
    __syncthreads();
    const int   len  = s_len;
    const float lenf = (float)len;

    const int j0 = tid * 2;
    const int i0 = b * H + j0;

    const uint32_t bits0 = threefry_bits_partitionable((uint32_t)i0);
    const uint32_t bits1 = threefry_bits_partitionable((uint32_t)(i0 + 1));
    const float u0 = __uint_as_float((bits0 >> 9) | 0x3f800000u) - 1.0f;
    const float u1 = __uint_as_float((bits1 >> 9) | 0x3f800000u) - 1.0f;
    int idx0 = (int)floorf(u0 * lenf);
    int idx1 = (int)floorf(u1 * lenf);
    if (idx0 > len - 1) idx0 = len - 1;
    if (idx1 > len - 1) idx1 = len - 1;

    const size_t rowb = (size_t)b * SEQ * H;
    const float e0 = __ldcg(&tokens[rowb + (size_t)idx0 * H + j0]);
    const float e1 = __ldcg(&tokens[rowb + (size_t)idx1 * H + j0 + 1]);
    *reinterpret_cast<float2*>(&g_emb[i0]) = make_float2(e0, e1);
}

// ---------------------------------------------------------------------------
// Kernel 2: TF32 GEMM, R8 config (BM=64, BN=64, BK=16, 4-stage cp.async,
// 144 blocks x 256 threads). Launched with PDL; spins at
// cudaGridDependencySynchronize() until prep completes.
// ---------------------------------------------------------------------------
#define BK     16
#define NIT    (H / BK)   // 48
#define NSTAGE 4
#define APAD   20
#define BPAD   72
#define A_WORDS (64 * APAD)   // 1280
#define B_WORDS (BK * BPAD)   // 1152

__device__ __forceinline__ void cp16(uint32_t saddr, const void* gaddr) {
    asm volatile("cp.async.ca.shared.global [%0], [%1], 16;\n"
                 :: "r"(saddr), "l"(gaddr));
}
__device__ __forceinline__ void cp_commit() {
    asm volatile("cp.async.commit_group;\n");
}
template <int N>
__device__ __forceinline__ void cp_wait() {
    asm volatile("cp.async.wait_group %0;\n" :: "n"(N));
}

__device__ __forceinline__ void mma_tf32(float* d, const uint32_t* a, const uint32_t* b) {
    asm volatile(
        "mma.sync.aligned.m16n8k8.row.col.f32.tf32.tf32.f32 "
        "{%0,%1,%2,%3}, {%4,%5,%6,%7}, {%8,%9}, {%0,%1,%2,%3};\n"
        : "+f"(d[0]), "+f"(d[1]), "+f"(d[2]), "+f"(d[3])
        : "r"(a[0]), "r"(a[1]), "r"(a[2]), "r"(a[3]), "r"(b[0]), "r"(b[1]));
}

__global__ void __launch_bounds__(256, 1)
gemm_tf32_kernel(const float* __restrict__ cls,
                 const float* __restrict__ W) {
    const int g  = blockIdx.y >> 2;             // group 0..2
    const int m0 = (blockIdx.y & 3) * 64;
    const int n0 = blockIdx.x * 64;

    __shared__ uint32_t As[NSTAGE][A_WORDS];
    __shared__ uint32_t Bs[NSTAGE][B_WORDS];

    const int tid  = threadIdx.x;
    const int warp = tid >> 5;
    const int lane = tid & 31;
    const int wm   = (warp & 1) * 32;
    const int wn   = (warp >> 1) * 16;
    const int grp  = lane >> 2;
    const int tig  = lane & 3;

    const int a_r = tid >> 2;
    const int a_c = (tid & 3) * 4;
    const int b_r = tid >> 4;
    const int b_c = (tid & 15) * 4;

    // setup done; wait for prep (g_emb) before reading any dependent data
    cudaGridDependencySynchronize();

    const float* __restrict__ A  = (g == 2) ? g_emb : cls;
    const float* __restrict__ Wg = W + (g == 0 ? 0 : (size_t)H * H);

    const float* a_src = &A[(m0 + a_r) * H + a_c];
    const float* b_src = &Wg[(size_t)b_r * H + n0 + b_c];

    const uint32_t s_as = (uint32_t)__cvta_generic_to_shared(&As[0][0]) +
                          (uint32_t)((a_r * APAD + a_c) * 4);
    const uint32_t s_bs = (uint32_t)__cvta_generic_to_shared(&Bs[0][0]) +
                          (uint32_t)((b_r * BPAD + b_c) * 4);

    float acc[2][2][4];
#pragma unroll
    for (int mi = 0; mi < 2; mi++)
#pragma unroll
        for (int ni = 0; ni < 2; ni++)
#pragma unroll
            for (int r = 0; r < 4; r++) acc[mi][ni][r] = 0.0f;

#pragma unroll
    for (int s = 0; s < NSTAGE - 1; s++) {
        cp16(s_as + (uint32_t)(s * A_WORDS * 4), a_src + s * BK);
        cp16(s_bs + (uint32_t)(s * B_WORDS * 4), b_src + (size_t)(s * BK) * H);
        cp_commit();
    }

    for (int it = 0; it < NIT; it++) {
        cp_wait<NSTAGE - 2>();
        __syncthreads();

        const int nx = it + NSTAGE - 1;
        if (nx < NIT) {
            const int buf = nx & (NSTAGE - 1);
            cp16(s_as + (uint32_t)(buf * A_WORDS * 4), a_src + nx * BK);
            cp16(s_bs + (uint32_t)(buf * B_WORDS * 4), b_src + (size_t)(nx * BK) * H);
        }
        cp_commit();

        const uint32_t* Asb = As[it & (NSTAGE - 1)];
        const uint32_t* Bsb = Bs[it & (NSTAGE - 1)];
#pragma unroll
        for (int ks = 0; ks < BK; ks += 8) {
            uint32_t afr[2][4];
#pragma unroll
            for (int mi = 0; mi < 2; mi++) {
                const int rbase = (wm + mi * 16 + grp) * APAD + ks + tig;
                afr[mi][0] = Asb[rbase];
                afr[mi][1] = Asb[rbase + 8 * APAD];
                afr[mi][2] = Asb[rbase + 4];
                afr[mi][3] = Asb[rbase + 8 * APAD + 4];
            }
            uint32_t bfr[2][2];
#pragma unroll
            for (int ni = 0; ni < 2; ni++) {
                const int cbase = (ks + tig) * BPAD + wn + ni * 8 + grp;
                bfr[ni][0] = Bsb[cbase];
                bfr[ni][1] = Bsb[cbase + 4 * BPAD];
            }
#pragma unroll
            for (int mi = 0; mi < 2; mi++)
#pragma unroll
                for (int ni = 0; ni < 2; ni++)
                    mma_tf32(acc[mi][ni], afr[mi], bfr[ni]);
        }
    }

    float* __restrict__ Cp = g_S + (size_t)g * BS * H;
#pragma unroll
    for (int mi = 0; mi < 2; mi++) {
#pragma unroll
        for (int ni = 0; ni < 2; ni++) {
            const int col = n0 + wn + ni * 8 + tig * 2;
            const int r0  = m0 + wm + mi * 16 + grp;
            *reinterpret_cast<float2*>(&Cp[(size_t)r0 * H + col]) =
                make_float2(acc[mi][ni][0], acc[mi][ni][1]);
            *reinterpret_cast<float2*>(&Cp[(size_t)(r0 + 8) * H + col]) =
                make_float2(acc[mi][ni][2], acc[mi][ni][3]);
        }
    }
}

// ---------------------------------------------------------------------------
// Kernel 3: fused epilogue (R8 config). PDL: spins until GEMM completes
// (transitively ordered after prep).
// ---------------------------------------------------------------------------
__global__ void __launch_bounds__(768, 2)
epilogue_kernel(const float* __restrict__ cls,
                const float* __restrict__ bias,
                const float* __restrict__ v,
                float*       __restrict__ out) {
    const int b   = blockIdx.x;
    const int tid = threadIdx.x;
    const size_t base = (size_t)b * H + tid;

    cudaGridDependencySynchronize();

    const float cv = cls[base];
    const float ev = g_emb[base];
    const float a  = g_S[base];
    const float bb = g_S[(size_t)BS * H + base];
    const float c  = g_S[(size_t)2 * BS * H + base];
    const float bi = bias[tid];
    const float vv = v[tid];

    float p0 = fast_tanh(a + bb + bi) * vv;
    float p1 = fast_tanh(a + c  + bi) * vv;

#pragma unroll
    for (int off = 16; off > 0; off >>= 1) {
        p0 += __shfl_down_sync(0xffffffffu, p0, off);
        p1 += __shfl_down_sync(0xffffffffu, p1, off);
    }
    __shared__ float r0[24], r1[24];
    __shared__ float s_alpha;
    const int w = tid >> 5, l = tid & 31;
    if (l == 0) { r0[w] = p0; r1[w] = p1; }
    __syncthreads();
    if (tid == 0) {
        float e0 = 0.0f, e1 = 0.0f;
#pragma unroll
        for (int i = 0; i < 24; i++) { e0 += r0[i]; e1 += r1[i]; }
        const float m  = fmaxf(e0, e1);
        const float w0 = __expf(e0 - m);
        const float w1 = __expf(e1 - m);
        s_alpha = w0 / (w0 + w1);
    }
    __syncthreads();
    const float a0 = s_alpha;
    out[base] = a0 * cv + (1.0f - a0) * ev;
}

// ---------------------------------------------------------------------------
// kernel_launch — inputs identified BY ELEMENT COUNT.
// GEMM + epilogue use Programmatic Dependent Launch (pre-launch + device-side
// dependency sync) to collapse inter-kernel gaps.
// ---------------------------------------------------------------------------
extern "C" void kernel_launch(void* const* d_in, const int* in_sizes, int n_in,
                              void* d_out, int out_size) {
    const float* tokens = nullptr;
    const float* cls    = nullptr;
    const int*   mask   = nullptr;
    const float* W      = nullptr;
    const float* bias   = nullptr;
    const float* v      = nullptr;

    for (int i = 0; i < n_in; i++) {
        const int sz = in_sizes[i];
        if      (sz == BS * SEQ * H) tokens = (const float*)d_in[i];
        else if (sz == BS * H)       cls    = (const float*)d_in[i];
        else if (sz == BS * SEQ)     mask   = (const int*)  d_in[i];
        else if (sz == 2 * H * H)    W      = (const float*)d_in[i];
        else if (sz == H) {
            if (bias == nullptr)     bias   = (const float*)d_in[i];
            else                     v      = (const float*)d_in[i];
        }
    }
    float* out = (float*)d_out;

    prep_kernel<<<BS, 384>>>(tokens, mask);

    cudaLaunchAttribute pdl_attr;
    pdl_attr.id = cudaLaunchAttributeProgrammaticStreamSerialization;
    pdl_attr.val.programmaticStreamSerializationAllowed = 1;

    {
        cudaLaunchConfig_t cfg = {};
        cfg.gridDim  = dim3(H / 64, 12);
        cfg.blockDim = dim3(256);
        cfg.attrs    = &pdl_attr;
        cfg.numAttrs = 1;
        cudaLaunchKernelEx(&cfg, gemm_tf32_kernel, cls, W);
    }
    {
        cudaLaunchConfig_t cfg = {};
        cfg.gridDim  = dim3(BS);
        cfg.blockDim = dim3(768);
        cfg.attrs    = &pdl_attr;
        cfg.numAttrs = 1;
        cudaLaunchKernelEx(&cfg, epilogue_kernel, cls, bias, v, out);
    }
}